// round 17
// baseline (speedup 1.0000x reference)
#include <cuda_runtime.h>
#include <cuda_bf16.h>
#include <math.h>
#include <stdint.h>

// Shapes (fixed by the benchmark)
#define BB 2
#define SS 8192
#define DD 64
#define D2 128           // 2*D

// Smem: Q tiles (2 x 64KB) + 2-slot K ring (2 x 32KB)
#define OFF_QH 0          // 256 x 128 bf16 = 64KB
#define OFF_QL 65536
#define OFFK(s) (131072 + (s) * 32768)  // per slot: KH at +0, KL at +16384
#define SM_BYTES 196608

// Work items: 32 q-tiles (256 rows) per batch; tile m' has NJ=4m'+4 kv-steps,
// split into cn = m'/10+1 chunks (each <= 40 steps).
// NWORK per batch = 10*1 + 10*2 + 10*3 + 2*4 = 68.
#define NWORK 68
#define NSLICE 4

// EMA chunking
#define EMA_CHUNK 128
#define EMA_NCHUNK (SS / EMA_CHUNK)   // 64

// Scratch (static device globals -- no allocation allowed)
__device__ __nv_bfloat16 g_Qh[BB * SS * D2];
__device__ __nv_bfloat16 g_Ql[BB * SS * D2];
__device__ __nv_bfloat16 g_Kh[BB * SS * D2];
__device__ __nv_bfloat16 g_Kl[BB * SS * D2];
__device__ float g_O4[NSLICE][BB * SS * DD];  // unnormalized folded O per chunk slice
__device__ float g_Ls4[NSLICE][BB * SS];      // row exp-sums per chunk slice

// ---------------- helpers ----------------
__device__ __forceinline__ uint32_t smem_u32(const void* p) {
    uint32_t a;
    asm("{ .reg .u64 t; cvta.to.shared.u64 t, %1; cvt.u32.u64 %0, t; }"
        : "=r"(a) : "l"(p));
    return a;
}
__device__ __forceinline__ void ldsm4(uint32_t* r, uint32_t addr) {
    asm volatile("ldmatrix.sync.aligned.m8n8.x4.shared.b16 {%0,%1,%2,%3}, [%4];"
        : "=r"(r[0]), "=r"(r[1]), "=r"(r[2]), "=r"(r[3]) : "r"(addr));
}
__device__ __forceinline__ void ldsm4t(uint32_t* r, uint32_t addr) {
    asm volatile("ldmatrix.sync.aligned.m8n8.x4.trans.shared.b16 {%0,%1,%2,%3}, [%4];"
        : "=r"(r[0]), "=r"(r[1]), "=r"(r[2]), "=r"(r[3]) : "r"(addr));
}
__device__ __forceinline__ void mma16816(float* c, const uint32_t* a, const uint32_t* b) {
    asm volatile(
        "mma.sync.aligned.m16n8k16.row.col.f32.bf16.bf16.f32 "
        "{%0,%1,%2,%3}, {%4,%5,%6,%7}, {%8,%9}, {%0,%1,%2,%3};"
        : "+f"(c[0]), "+f"(c[1]), "+f"(c[2]), "+f"(c[3])
        : "r"(a[0]), "r"(a[1]), "r"(a[2]), "r"(a[3]), "r"(b[0]), "r"(b[1]));
}
// pack (x -> lo, y -> hi) as bf16x2, plus residual pack
__device__ __forceinline__ void split2(float x, float y, uint32_t& h, uint32_t& l) {
    asm("cvt.rn.bf16x2.f32 %0, %1, %2;" : "=r"(h) : "f"(y), "f"(x));
    float hx = __uint_as_float(h << 16);
    float hy = __uint_as_float(h & 0xffff0000u);
    asm("cvt.rn.bf16x2.f32 %0, %1, %2;" : "=r"(l) : "f"(y - hy), "f"(x - hx));
}
// async copy of one K tile (hi+lo, 32KB) into ring slot base kbase_u
__device__ __forceinline__ void issue_ktile(const char* Khg, const char* Klg,
                                            uint32_t kbase_u, int k0, int tid) {
    #pragma unroll
    for (int e0 = 0; e0 < 1024; e0 += 256) {
        int e = e0 + tid;
        int r = e >> 4, u = e & 15;
        uint32_t so = (uint32_t)(r * 256 + ((u ^ (r & 7)) << 4));
        const char* gh = Khg + (size_t)(k0 + r) * 256 + (size_t)u * 16;
        const char* gl = Klg + (size_t)(k0 + r) * 256 + (size_t)u * 16;
        asm volatile("cp.async.cg.shared.global [%0], [%1], 16;"
                     :: "r"(kbase_u + so), "l"(gh));
        asm volatile("cp.async.cg.shared.global [%0], [%1], 16;"
                     :: "r"(kbase_u + 16384 + so), "l"(gl));
    }
}

// -------------------- Kernel 1: prep Q (LUT cos) and K, bf16 hi/lo --------------------
__global__ void prep_kernel(const float* __restrict__ sr,
                            const float* __restrict__ si,
                            const float* __restrict__ pos,
                            const float* __restrict__ w_q,
                            const float* __restrict__ b_q) {
    const float PHI_F     = (float)1.6180339887498948482;
    const float INV2PI    = (float)(1.0 / 6.283185307179586476925286766559);
    const float LUTN_F    = 4096.0f;
    const float ANG_STEP  = (float)(6.283185307179586476925286766559 / 4096.0);

    int idx = blockIdx.x * blockDim.x + threadIdx.x;   // over B*S*D
    if (idx >= BB * SS * DD) return;
    int d = idx & (DD - 1);
    int s = (idx >> 6) & (SS - 1);
    int b = idx >> 19;

    float wl   = 1.0f + fabsf(w_q[d]);
    float bq   = b_q[d];
    float tphi = __fmul_rn(pos[s], PHI_F);

    float xr = sr[idx];
    float xi = si[idx];

    float thr = __fadd_rn(__fadd_rn(__fdiv_rn(xr, wl), bq), tphi);
    float thi = __fadd_rn(__fadd_rn(__fdiv_rn(xi, wl), bq), tphi);

    float fr = __fmul_rn(thr, INV2PI);
    fr = __fsub_rn(fr, floorf(fr));
    int ir = (int)floorf(__fmul_rn(fr, LUTN_F));
    ir = ir < 0 ? 0 : (ir > 4095 ? 4095 : ir);
    float cr = cosf(__fmul_rn((float)ir, ANG_STEP));

    float fi = __fmul_rn(thi, INV2PI);
    fi = __fsub_rn(fi, floorf(fi));
    int ii = (int)floorf(__fmul_rn(fi, LUTN_F));
    ii = ii < 0 ? 0 : (ii > 4095 ? 4095 : ii);
    float ci = cosf(__fmul_rn((float)ii, ANG_STEP));

    int base = (b * SS + s) * D2;

    __nv_bfloat16 h, l;
    h = __float2bfloat16_rn(cr); l = __float2bfloat16_rn(cr - __bfloat162float(h));
    g_Qh[base + d] = h; g_Ql[base + d] = l;
    h = __float2bfloat16_rn(ci); l = __float2bfloat16_rn(ci - __bfloat162float(h));
    g_Qh[base + d + DD] = h; g_Ql[base + d + DD] = l;
    h = __float2bfloat16_rn(xr); l = __float2bfloat16_rn(xr - __bfloat162float(h));
    g_Kh[base + d] = h; g_Kl[base + d] = l;
    h = __float2bfloat16_rn(xi); l = __float2bfloat16_rn(xi - __bfloat162float(h));
    g_Kh[base + d + DD] = h; g_Kl[base + d + DD] = l;
}

// ============ Kernel 2: causal flash attention, 256-row tiles, 32 rows/warp ============
__global__ __launch_bounds__(256, 1) void attn_mma() {
    extern __shared__ char sm[];
    const uint32_t su = smem_u32(sm);
    const uint32_t sQh_u = su + OFF_QH, sQl_u = su + OFF_QL;

    const int tid  = threadIdx.x;
    const int wid  = tid >> 5;
    const int lane = tid & 31;
    const int lr = lane & 7, q4 = lane >> 3;
    const int g  = lane >> 2, t = lane & 3;

    // ---- work item decode: largest tiles first ----
    const int bid = blockIdx.x;
    const int b   = bid & 1;
    const int w   = (NWORK - 1) - (bid >> 1);   // 0..67
    int m2, ci, cn;
    if (w < 10)      { m2 = w;                          ci = 0;      cn = 1; }
    else if (w < 30) { int q = w - 10; m2 = 10 + (q >> 1); ci = q & 1;  cn = 2; }
    else if (w < 60) { int q = w - 30; m2 = 20 + q / 3;    ci = q % 3;  cn = 3; }
    else             { int q = w - 60; m2 = 30 + (q >> 2); ci = q & 3;  cn = 4; }
    const int NJ = 4 * m2 + 4;
    const int q0 = m2 << 8;
    const int j0 = (ci * NJ) / cn;
    const int j1 = ((ci + 1) * NJ) / cn;

    const char* Qhg = (const char*)(g_Qh + b * (SS * D2) + q0 * D2);
    const char* Qlg = (const char*)(g_Ql + b * (SS * D2) + q0 * D2);
    const char* Khg = (const char*)(g_Kh + b * (SS * D2));
    const char* Klg = (const char*)(g_Kl + b * (SS * D2));

    // ---- load Q tiles (256 rows x 256B, hi+lo), swizzled ----
    for (int e = tid; e < 4096; e += 256) {
        int r = e >> 4, u = e & 15;
        int so = r * 256 + ((u ^ (r & 7)) << 4);
        int go = r * 256 + u * 16;
        *(uint4*)(sm + OFF_QH + so) = *(const uint4*)(Qhg + go);
        *(uint4*)(sm + OFF_QL + so) = *(const uint4*)(Qlg + go);
    }

    // ---- prologue: prefetch first K tile into ring slot 0 ----
    issue_ktile(Khg, Klg, su + OFFK(0), j0 << 6, tid);
    asm volatile("cp.async.commit_group;" ::: "memory");

    // A-frag (Q) lane addressing (two 16-row blocks per warp)
    const int rowA0 = wid * 32 + lr + 8 * (q4 & 1);
    const int swA = rowA0 & 7;                   // +16 preserves &7
    const int unitAx = q4 >> 1;
    const uint32_t aRow0 = (uint32_t)rowA0 * 256u;
    const uint32_t aRow1 = aRow0 + 4096u;        // +16 rows
    // B-frag (K rows as n) lane addressing
    const int rowBo = lr + 8 * (q4 >> 1);
    const int unitBx = q4 & 1;
    // V-frag (trans) lane addressing
    const int rowVo = lr + 8 * (q4 & 1);
    const int unitVx = q4 >> 1;

    float o0[16][4], o1[16][4];
    #pragma unroll
    for (int i = 0; i < 16; i++)
        #pragma unroll
        for (int c = 0; c < 4; c++) { o0[i][c] = 0.f; o1[i][c] = 0.f; }
    float l00 = 0.f, l01 = 0.f, l10 = 0.f, l11 = 0.f;

    const float SC = 0.0883883476483184405501f;  // 1/sqrt(128)
    const int rb0row = q0 + wid * 32;            // first row of block 0
    const int row0 = rb0row + g;                 // lane row, block 0
    const int row1 = row0 + 16;                  // lane row, block 1

    for (int j = j0; j < j1; ++j) {
        const int idx  = j - j0;
        const uint32_t kb  = su + (uint32_t)OFFK(idx & 1);
        const uint32_t kbl = kb + 16384u;

        // retire tile j; barrier also frees the other slot (tile j-1 done by all)
        asm volatile("cp.async.wait_group 0;" ::: "memory");
        __syncthreads();
        if (j + 1 < j1) {
            issue_ktile(Khg, Klg, su + (uint32_t)OFFK((idx + 1) & 1), (j + 1) << 6, tid);
            asm volatile("cp.async.commit_group;" ::: "memory");
        }

        const int k0 = j << 6;

        // ---- QK: S[32x64] = Qh.Kh + Qh.Kl + Ql.Kh (K frags shared across row blocks) ----
        float s0[8][4], s1[8][4];
        #pragma unroll
        for (int i = 0; i < 8; i++)
            #pragma unroll
            for (int c = 0; c < 4; c++) { s0[i][c] = 0.f; s1[i][c] = 0.f; }

        #pragma unroll
        for (int kbk = 0; kbk < 8; kbk++) {
            uint32_t off = (uint32_t)(((2 * kbk + unitAx) ^ swA) << 4);
            uint32_t aH0[4], aL0[4], aH1[4], aL1[4];
            ldsm4(aH0, sQh_u + aRow0 + off);
            ldsm4(aL0, sQl_u + aRow0 + off);
            ldsm4(aH1, sQh_u + aRow1 + off);
            ldsm4(aL1, sQl_u + aRow1 + off);
            #pragma unroll
            for (int nb2 = 0; nb2 < 4; nb2++) {
                int rB = nb2 * 16 + rowBo;
                uint32_t bo = (uint32_t)(rB * 256 + (((2 * kbk + unitBx) ^ (rB & 7)) << 4));
                uint32_t bH[4], bL[4];
                ldsm4(bH, kb + bo);
                ldsm4(bL, kbl + bo);
                mma16816(s0[2 * nb2],     aH0, &bH[0]);
                mma16816(s0[2 * nb2],     aH0, &bL[0]);
                mma16816(s0[2 * nb2],     aL0, &bH[0]);
                mma16816(s0[2 * nb2 + 1], aH0, &bH[2]);
                mma16816(s0[2 * nb2 + 1], aH0, &bL[2]);
                mma16816(s0[2 * nb2 + 1], aL0, &bH[2]);
                mma16816(s1[2 * nb2],     aH1, &bH[0]);
                mma16816(s1[2 * nb2],     aH1, &bL[0]);
                mma16816(s1[2 * nb2],     aL1, &bH[0]);
                mma16816(s1[2 * nb2 + 1], aH1, &bH[2]);
                mma16816(s1[2 * nb2 + 1], aH1, &bL[2]);
                mma16816(s1[2 * nb2 + 1], aL1, &bH[2]);
            }
        }

        // ---- epilogue per row block: mask + exp + P frags ----
        uint32_t ph0a[8], ph1a[8], pl0a[8], pl1a[8];   // block 0
        uint32_t ph0b[8], ph1b[8], pl0b[8], pl1b[8];   // block 1
        {
            const bool fullA = (k0 + 63 <= rb0row);
            #pragma unroll
            for (int nb = 0; nb < 8; nb++) {
                float e0, e1, e2, e3;
                if (fullA) {
                    e0 = __expf(s0[nb][0] * SC);
                    e1 = __expf(s0[nb][1] * SC);
                    e2 = __expf(s0[nb][2] * SC);
                    e3 = __expf(s0[nb][3] * SC);
                } else {
                    int col = k0 + nb * 8 + 2 * t;
                    e0 = (col     <= row0    ) ? __expf(s0[nb][0] * SC) : 0.f;
                    e1 = (col + 1 <= row0    ) ? __expf(s0[nb][1] * SC) : 0.f;
                    e2 = (col     <= row0 + 8) ? __expf(s0[nb][2] * SC) : 0.f;
                    e3 = (col + 1 <= row0 + 8) ? __expf(s0[nb][3] * SC) : 0.f;
                }
                l00 += e0 + e1;
                l01 += e2 + e3;
                split2(e0, e1, ph0a[nb], pl0a[nb]);
                split2(e2, e3, ph1a[nb], pl1a[nb]);
            }
            const bool fullB = (k0 + 63 <= rb0row + 16);
            #pragma unroll
            for (int nb = 0; nb < 8; nb++) {
                float e0, e1, e2, e3;
                if (fullB) {
                    e0 = __expf(s1[nb][0] * SC);
                    e1 = __expf(s1[nb][1] * SC);
                    e2 = __expf(s1[nb][2] * SC);
                    e3 = __expf(s1[nb][3] * SC);
                } else {
                    int col = k0 + nb * 8 + 2 * t;
                    e0 = (col     <= row1    ) ? __expf(s1[nb][0] * SC) : 0.f;
                    e1 = (col + 1 <= row1    ) ? __expf(s1[nb][1] * SC) : 0.f;
                    e2 = (col     <= row1 + 8) ? __expf(s1[nb][2] * SC) : 0.f;
                    e3 = (col + 1 <= row1 + 8) ? __expf(s1[nb][3] * SC) : 0.f;
                }
                l10 += e0 + e1;
                l11 += e2 + e3;
                split2(e0, e1, ph0b[nb], pl0b[nb]);
                split2(e2, e3, ph1b[nb], pl1b[nb]);
            }
        }

        // ---- PV: O[32x128] += Ph.Vh + Ph.Vl + Pl.Vh (V frags shared across blocks) ----
        #pragma unroll
        for (int kbk = 0; kbk < 4; kbk++) {
            uint32_t aPhA[4] = { ph0a[2*kbk], ph1a[2*kbk], ph0a[2*kbk+1], ph1a[2*kbk+1] };
            uint32_t aPlA[4] = { pl0a[2*kbk], pl1a[2*kbk], pl0a[2*kbk+1], pl1a[2*kbk+1] };
            uint32_t aPhB[4] = { ph0b[2*kbk], ph1b[2*kbk], ph0b[2*kbk+1], ph1b[2*kbk+1] };
            uint32_t aPlB[4] = { pl0b[2*kbk], pl1b[2*kbk], pl0b[2*kbk+1], pl1b[2*kbk+1] };
            #pragma unroll
            for (int db2 = 0; db2 < 8; db2++) {
                int rV = kbk * 16 + rowVo;
                uint32_t vo = (uint32_t)(rV * 256 + (((2 * db2 + unitVx) ^ (rV & 7)) << 4));
                uint32_t bH[4], bL[4];
                ldsm4t(bH, kb + vo);
                ldsm4t(bL, kbl + vo);
                mma16816(o0[2 * db2],     aPhA, &bH[0]);
                mma16816(o0[2 * db2],     aPhA, &bL[0]);
                mma16816(o0[2 * db2],     aPlA, &bH[0]);
                mma16816(o0[2 * db2 + 1], aPhA, &bH[2]);
                mma16816(o0[2 * db2 + 1], aPhA, &bL[2]);
                mma16816(o0[2 * db2 + 1], aPlA, &bH[2]);
                mma16816(o1[2 * db2],     aPhB, &bH[0]);
                mma16816(o1[2 * db2],     aPhB, &bL[0]);
                mma16816(o1[2 * db2],     aPlB, &bH[0]);
                mma16816(o1[2 * db2 + 1], aPhB, &bH[2]);
                mma16816(o1[2 * db2 + 1], aPhB, &bL[2]);
                mma16816(o1[2 * db2 + 1], aPlB, &bH[2]);
            }
        }
    }

    // ---- row-sum reduce (across the 4 lanes sharing a row) ----
    l00 += __shfl_xor_sync(0xffffffffu, l00, 1);
    l00 += __shfl_xor_sync(0xffffffffu, l00, 2);
    l01 += __shfl_xor_sync(0xffffffffu, l01, 1);
    l01 += __shfl_xor_sync(0xffffffffu, l01, 2);
    l10 += __shfl_xor_sync(0xffffffffu, l10, 1);
    l10 += __shfl_xor_sync(0xffffffffu, l10, 2);
    l11 += __shfl_xor_sync(0xffffffffu, l11, 1);
    l11 += __shfl_xor_sync(0xffffffffu, l11, 2);

    // ---- fold (c and c+64) in registers, write slice ci ----
    float* Og = &g_O4[ci][b * (SS * DD)];
    #pragma unroll
    for (int dt = 0; dt < 8; dt++) {
        int c = dt * 8 + 2 * t;   // 0..63
        float a0 = o0[dt][0] + o0[dt + 8][0];
        float a1 = o0[dt][1] + o0[dt + 8][1];
        float a2 = o0[dt][2] + o0[dt + 8][2];
        float a3 = o0[dt][3] + o0[dt + 8][3];
        *(float2*)(Og + row0 * DD + c)       = make_float2(a0, a1);
        *(float2*)(Og + (row0 + 8) * DD + c) = make_float2(a2, a3);
        float b0 = o1[dt][0] + o1[dt + 8][0];
        float b1 = o1[dt][1] + o1[dt + 8][1];
        float b2 = o1[dt][2] + o1[dt + 8][2];
        float b3 = o1[dt][3] + o1[dt + 8][3];
        *(float2*)(Og + row1 * DD + c)       = make_float2(b0, b1);
        *(float2*)(Og + (row1 + 8) * DD + c) = make_float2(b2, b3);
    }
    if (t == 0) {
        g_Ls4[ci][b * SS + row0]      = l00;
        g_Ls4[ci][b * SS + row0 + 8]  = l01;
        g_Ls4[ci][b * SS + row1]      = l10;
        g_Ls4[ci][b * SS + row1 + 8]  = l11;
    }
}

// ------ Kernel 3: combine slices + chunked EMA (windowed, batch-prefetched) ------
__global__ __launch_bounds__(64, 1) void ema_chunk_kernel(
        const float* __restrict__ alpha_p, float* __restrict__ out) {
    const int d     = threadIdx.x;              // 0..63
    const int b     = blockIdx.x >> 6;
    const int chunk = blockIdx.x & 63;

    const float alpha = alpha_p[0];
    const float a  = 1.0f / (1.0f + expf(-alpha));
    const float na = 1.0f - a;

    // adaptive lookback: (1-a)^lb <= 2^-40, rounded to 8, clamped
    float dl = -log2f(na);
    int lb = (int)ceilf(40.0f / fmaxf(dl, 1e-6f));
    lb = (lb + 7) & ~7;
    lb = lb < 8 ? 8 : (lb > 2048 ? 2048 : lb);

    const int t0     = chunk * EMA_CHUNK;
    int tstart       = t0 - lb;
    if (tstart < 0) tstart = 0;
    const int tend   = t0 + EMA_CHUNK;

    const int bO = b * (SS * DD);
    const int bL = b * SS;
    float* __restrict__ Ob = out + b * (SS * DD);

    float e = 0.f;
    for (int t = tstart; t < tend; t += 8) {
        float z[8];
        #pragma unroll
        for (int i = 0; i < 8; i++) {
            const int tt = t + i;
            const int cn = (tt >> 8) / 10 + 1;   // slices for this 256-row q-tile
            float num = g_O4[0][bO + tt * DD + d];
            float L   = g_Ls4[0][bL + tt];
            for (int s2 = 1; s2 < cn; s2++) {
                num += g_O4[s2][bO + tt * DD + d];
                L   += g_Ls4[s2][bL + tt];
            }
            z[i] = num / L;
        }
        #pragma unroll
        for (int i = 0; i < 8; i++) {
            e = a * z[i] + na * e;
            if (t + i >= t0) Ob[(t + i) * DD + d] = e;
        }
    }
}

// -------------------- launch --------------------
extern "C" void kernel_launch(void* const* d_in, const int* in_sizes, int n_in,
                              void* d_out, int out_size) {
    const float* sr    = (const float*)d_in[0];
    const float* si    = (const float*)d_in[1];
    const float* pos   = (const float*)d_in[2];
    const float* w_q   = (const float*)d_in[3];
    const float* b_q   = (const float*)d_in[4];
    const float* alpha = (const float*)d_in[5];
    float* out = (float*)d_out;

    (void)in_sizes; (void)n_in; (void)out_size;

    cudaFuncSetAttribute(attn_mma,
                         cudaFuncAttributeMaxDynamicSharedMemorySize, SM_BYTES);

    const int nprep = BB * SS * DD;
    prep_kernel<<<(nprep + 255) / 256, 256>>>(sr, si, pos, w_q, b_q);
    attn_mma<<<2 * NWORK, 256, SM_BYTES>>>();
    ema_chunk_kernel<<<BB * EMA_NCHUNK, 64>>>(alpha, out);
}